// round 4
// baseline (speedup 1.0000x reference)
#include <cuda_runtime.h>

#define Bv 8
#define Cv 128
#define Hv 128
#define Wv 128
#define KK 9
#define ROWS 32   // rows per strip (conv)

typedef unsigned long long u64;

// Scratch (no allocations allowed in kernel_launch)
__device__ float g_pooled[Bv * Cv];
__device__ float g_kern[Bv * Cv * KK];

// ---- packed f32x2 helpers (Blackwell FFMA2 via PTX) ------------------------
__device__ __forceinline__ u64 pack2(float lo, float hi) {
    u64 r;
    asm("mov.b64 %0, {%1, %2};" : "=l"(r) : "f"(lo), "f"(hi));
    return r;
}
__device__ __forceinline__ u64 fma2(u64 a, u64 b, u64 c) {
    u64 d;
    asm("fma.rn.f32x2 %0, %1, %2, %3;" : "=l"(d) : "l"(a), "l"(b), "l"(c));
    return d;
}
__device__ __forceinline__ u64 mul2(u64 a, u64 b) {
    u64 d;
    asm("mul.rn.f32x2 %0, %1, %2;" : "=l"(d) : "l"(a), "l"(b));
    return d;
}
// Streaming store: evict-first in L2 so output writes don't displace x.
__device__ __forceinline__ void stcs64(float* p, u64 v) {
    asm volatile("st.global.cs.b64 [%0], %1;" :: "l"(p), "l"(v) : "memory");
}

// ---------------------------------------------------------------------------
// Kernel 1: global average pool per (b,c) plane. 1024 blocks x 256 threads.
// Default caching: populates L2 with x for the conv pass.
// ---------------------------------------------------------------------------
__global__ void pool_kernel(const float* __restrict__ x) {
    const int plane = blockIdx.x;  // b*C + c
    const float4* xp = reinterpret_cast<const float4*>(x + (size_t)plane * Hv * Wv);

    float sum = 0.f;
#pragma unroll
    for (int i = 0; i < 16; i++) {
        float4 v = xp[threadIdx.x + i * 256];
        sum += (v.x + v.y) + (v.z + v.w);
    }

    __shared__ float sdata[8];
#pragma unroll
    for (int o = 16; o; o >>= 1) sum += __shfl_down_sync(0xffffffffu, sum, o);
    if ((threadIdx.x & 31) == 0) sdata[threadIdx.x >> 5] = sum;
    __syncthreads();
    if (threadIdx.x < 8) {
        sum = sdata[threadIdx.x];
#pragma unroll
        for (int o = 4; o; o >>= 1) sum += __shfl_down_sync(0xffu, sum, o);
        if (threadIdx.x == 0) g_pooled[plane] = sum * (1.f / (float)(Hv * Wv));
    }
}

// ---------------------------------------------------------------------------
// Kernel 2: fused 2-layer MLP, one block per batch, 512 threads (16 warps).
// Both layers warp-per-output with coalesced float4 weight-row loads.
// ---------------------------------------------------------------------------
__global__ void mlp_kernel(const float* __restrict__ w1, const float* __restrict__ b1,
                           const float* __restrict__ w2, const float* __restrict__ b2) {
    const int b = blockIdx.x;
    const int tid = threadIdx.x;
    const int wid = tid >> 5;      // 0..15
    const int lane = tid & 31;

    __shared__ float ps[Cv];
    __shared__ float hs[Cv];

    if (tid < Cv) ps[tid] = g_pooled[b * Cv + tid];
    __syncthreads();

    const float4 pv = *(const float4*)&ps[lane * 4];

    // Layer 1: 128 outputs / 16 warps = 8 per warp.
#pragma unroll
    for (int i = 0; i < 8; i++) {
        const int o = wid * 8 + i;
        const float4 wv = *(const float4*)(w1 + (size_t)o * Cv + lane * 4);
        float acc = wv.x * pv.x;
        acc = fmaf(wv.y, pv.y, acc);
        acc = fmaf(wv.z, pv.z, acc);
        acc = fmaf(wv.w, pv.w, acc);
#pragma unroll
        for (int s = 16; s; s >>= 1) acc += __shfl_xor_sync(0xffffffffu, acc, s);
        if (lane == 0) hs[o] = fmaxf(acc + b1[o], 0.f);
    }
    __syncthreads();

    const float4 hv = *(const float4*)&hs[lane * 4];

    // Layer 2: 1152 outputs / 16 warps = 72 per warp.
#pragma unroll 4
    for (int i = 0; i < 72; i++) {
        const int o = wid * 72 + i;
        const float4 wv = *(const float4*)(w2 + (size_t)o * Cv + lane * 4);
        float acc = wv.x * hv.x;
        acc = fmaf(wv.y, hv.y, acc);
        acc = fmaf(wv.z, hv.z, acc);
        acc = fmaf(wv.w, hv.w, acc);
#pragma unroll
        for (int s = 16; s; s >>= 1) acc += __shfl_xor_sync(0xffffffffu, acc, s);
        if (lane == 0) g_kern[b * Cv * KK + o] = acc + b2[o];
    }
}

// ---------------------------------------------------------------------------
// Kernel 3: dynamic depthwise 3x3 conv, packed f32x2 FMA + streaming stores.
// ---------------------------------------------------------------------------
__global__ void conv_kernel(const float* __restrict__ x, float* __restrict__ out) {
    const int plane = blockIdx.x >> 2;
    const int strip = blockIdx.x & 3;
    const int row0 = strip * ROWS;
    const int tx = threadIdx.x;            // 0..63
    const int ty = threadIdx.y;            // 0..1
    const int tid = ty * 64 + tx;          // 0..127

    __shared__ __align__(16) float s[ROWS + 2][Wv + 2];

    const float* xp = x + (size_t)plane * Hv * Wv;

#pragma unroll
    for (int r = 0; r < ROWS + 2; r++) {
        const int gr = row0 + r - 1;
        float v = (gr >= 0 && gr < Hv) ? xp[gr * Wv + tid] : 0.f;
        s[r][tid + 1] = v;
    }
    if (tid < ROWS + 2) {
        s[tid][0] = 0.f;
        s[tid][Wv + 1] = 0.f;
    }

    u64 w2p[9];
#pragma unroll
    for (int p = 0; p < 9; p++) {
        const float w = g_kern[plane * KK + p];
        w2p[p] = pack2(w, w);
    }

    __syncthreads();

    const int rbase = ty * (ROWS / 2);
    float* op = out + (size_t)plane * Hv * Wv + (size_t)(row0 + rbase) * Wv + 2 * tx;

#define LOADROW(r, m1, m0, p1)                                   \
    {                                                            \
        float2 lo = *(const float2*)&s[(r)][2 * tx];             \
        float2 hi = *(const float2*)&s[(r)][2 * tx + 2];         \
        (m1) = pack2(lo.x, lo.y);                                \
        (p1) = pack2(hi.x, hi.y);                                \
        (m0) = pack2(lo.y, hi.x);                                \
    }

    u64 a0, a1, a2, e0, e1, e2;
    LOADROW(rbase + 0, a0, a1, a2);
    LOADROW(rbase + 1, e0, e1, e2);

#pragma unroll
    for (int lr = 0; lr < ROWS / 2; lr++) {
        u64 c0, c1, c2;
        LOADROW(rbase + lr + 2, c0, c1, c2);

        u64 acc = mul2(a0, w2p[0]);
        acc = fma2(a1, w2p[1], acc);
        acc = fma2(a2, w2p[2], acc);
        acc = fma2(e0, w2p[3], acc);
        acc = fma2(e1, w2p[4], acc);
        acc = fma2(e2, w2p[5], acc);
        acc = fma2(c0, w2p[6], acc);
        acc = fma2(c1, w2p[7], acc);
        acc = fma2(c2, w2p[8], acc);

        stcs64(op + (size_t)lr * Wv, acc);   // streaming: don't evict x from L2

        a0 = e0; a1 = e1; a2 = e2;
        e0 = c0; e1 = c1; e2 = c2;
    }
#undef LOADROW
}

// ---------------------------------------------------------------------------
extern "C" void kernel_launch(void* const* d_in, const int* in_sizes, int n_in,
                              void* d_out, int out_size) {
    const float* x  = (const float*)d_in[0];
    const float* w1 = (const float*)d_in[1];
    const float* b1 = (const float*)d_in[2];
    const float* w2 = (const float*)d_in[3];
    const float* b2 = (const float*)d_in[4];
    float* out = (float*)d_out;

    pool_kernel<<<Bv * Cv, 256>>>(x);
    mlp_kernel<<<Bv, 512>>>(w1, b1, w2, b2);
    conv_kernel<<<Bv * Cv * (Hv / ROWS), dim3(64, 2)>>>(x, out);
}

// round 5
// speedup vs baseline: 1.2979x; 1.2979x over previous
#include <cuda_runtime.h>

#define Bv 8
#define Cv 128
#define Hv 128
#define Wv 128
#define KK 9
#define ROWS 32   // rows per strip (conv)

typedef unsigned long long u64;

// Scratch (no allocations allowed in kernel_launch)
__device__ float g_pooled[Bv * Cv];
__device__ float g_h[Bv * Cv];
__device__ float g_kern[Bv * Cv * KK];

// ---- packed f32x2 helpers (Blackwell FFMA2 via PTX) ------------------------
__device__ __forceinline__ u64 pack2(float lo, float hi) {
    u64 r;
    asm("mov.b64 %0, {%1, %2};" : "=l"(r) : "f"(lo), "f"(hi));
    return r;
}
__device__ __forceinline__ u64 fma2(u64 a, u64 b, u64 c) {
    u64 d;
    asm("fma.rn.f32x2 %0, %1, %2, %3;" : "=l"(d) : "l"(a), "l"(b), "l"(c));
    return d;
}
__device__ __forceinline__ u64 mul2(u64 a, u64 b) {
    u64 d;
    asm("mul.rn.f32x2 %0, %1, %2;" : "=l"(d) : "l"(a), "l"(b));
    return d;
}
// Streaming store: evict-first in L2 so output writes don't displace x.
__device__ __forceinline__ void stcs64(float* p, u64 v) {
    asm volatile("st.global.cs.b64 [%0], %1;" :: "l"(p), "l"(v) : "memory");
}

// ---------------------------------------------------------------------------
// Kernel 1: global average pool per (b,c) plane. 1024 blocks x 256 threads.
// Default caching: populates L2 with x for the conv pass.
// ---------------------------------------------------------------------------
__global__ void pool_kernel(const float* __restrict__ x) {
    const int plane = blockIdx.x;  // b*C + c
    const float4* xp = reinterpret_cast<const float4*>(x + (size_t)plane * Hv * Wv);

    float sum = 0.f;
#pragma unroll
    for (int i = 0; i < 16; i++) {
        float4 v = xp[threadIdx.x + i * 256];
        sum += (v.x + v.y) + (v.z + v.w);
    }

    __shared__ float sdata[8];
#pragma unroll
    for (int o = 16; o; o >>= 1) sum += __shfl_down_sync(0xffffffffu, sum, o);
    if ((threadIdx.x & 31) == 0) sdata[threadIdx.x >> 5] = sum;
    __syncthreads();
    if (threadIdx.x < 8) {
        sum = sdata[threadIdx.x];
#pragma unroll
        for (int o = 4; o; o >>= 1) sum += __shfl_down_sync(0xffu, sum, o);
        if (threadIdx.x == 0) g_pooled[plane] = sum * (1.f / (float)(Hv * Wv));
    }
}

// ---------------------------------------------------------------------------
// Kernel 2a: h = relu(pooled @ w1^T + b1), warp-per-output (coalesced w1 rows).
// ---------------------------------------------------------------------------
__global__ void h_kernel(const float* __restrict__ w1, const float* __restrict__ b1) {
    const int b = blockIdx.x;
    const int tid = threadIdx.x;
    const int wid = tid >> 5;
    const int lane = tid & 31;

    __shared__ float ps[Cv];
    ps[tid] = g_pooled[b * Cv + tid];
    __syncthreads();

    const float4 pv = *(const float4*)&ps[lane * 4];

#pragma unroll
    for (int i = 0; i < 32; i++) {
        const int o = wid * 32 + i;
        const float4 wv = *(const float4*)(w1 + (size_t)o * Cv + lane * 4);
        float acc = wv.x * pv.x;
        acc = fmaf(wv.y, pv.y, acc);
        acc = fmaf(wv.z, pv.z, acc);
        acc = fmaf(wv.w, pv.w, acc);
#pragma unroll
        for (int s = 16; s; s >>= 1) acc += __shfl_xor_sync(0xffffffffu, acc, s);
        if (lane == 0) g_h[b * Cv + o] = fmaxf(acc + b1[o], 0.f);
    }
}

// ---------------------------------------------------------------------------
// Kernel 2b: kern = h @ w2^T + b2, warp-per-output, spread over 288 blocks.
// ---------------------------------------------------------------------------
__global__ void kern_kernel(const float* __restrict__ w2, const float* __restrict__ b2) {
    const int b = blockIdx.x / 36;          // batch
    const int grp = blockIdx.x % 36;        // 32-output group within [0,1152)
    const int tid = threadIdx.x;
    const int wid = tid >> 5;
    const int lane = tid & 31;

    __shared__ float hs[Cv];
    hs[tid] = g_h[b * Cv + tid];
    __syncthreads();

    const float4 hv = *(const float4*)&hs[lane * 4];

#pragma unroll
    for (int i = 0; i < 8; i++) {
        const int o = grp * 32 + wid * 8 + i;   // [0, 1152)
        const float4 wv = *(const float4*)(w2 + (size_t)o * Cv + lane * 4);
        float acc = wv.x * hv.x;
        acc = fmaf(wv.y, hv.y, acc);
        acc = fmaf(wv.z, hv.z, acc);
        acc = fmaf(wv.w, hv.w, acc);
#pragma unroll
        for (int s = 16; s; s >>= 1) acc += __shfl_xor_sync(0xffffffffu, acc, s);
        if (lane == 0) g_kern[b * Cv * KK + o] = acc + b2[o];
    }
}

// ---------------------------------------------------------------------------
// Kernel 3: dynamic depthwise 3x3 conv, packed f32x2 FMA + streaming stores.
// ---------------------------------------------------------------------------
__global__ void conv_kernel(const float* __restrict__ x, float* __restrict__ out) {
    const int plane = blockIdx.x >> 2;
    const int strip = blockIdx.x & 3;
    const int row0 = strip * ROWS;
    const int tx = threadIdx.x;            // 0..63
    const int ty = threadIdx.y;            // 0..1
    const int tid = ty * 64 + tx;          // 0..127

    __shared__ __align__(16) float s[ROWS + 2][Wv + 2];

    const float* xp = x + (size_t)plane * Hv * Wv;

#pragma unroll
    for (int r = 0; r < ROWS + 2; r++) {
        const int gr = row0 + r - 1;
        float v = (gr >= 0 && gr < Hv) ? xp[gr * Wv + tid] : 0.f;
        s[r][tid + 1] = v;
    }
    if (tid < ROWS + 2) {
        s[tid][0] = 0.f;
        s[tid][Wv + 1] = 0.f;
    }

    u64 w2p[9];
#pragma unroll
    for (int p = 0; p < 9; p++) {
        const float w = g_kern[plane * KK + p];
        w2p[p] = pack2(w, w);
    }

    __syncthreads();

    const int rbase = ty * (ROWS / 2);
    float* op = out + (size_t)plane * Hv * Wv + (size_t)(row0 + rbase) * Wv + 2 * tx;

#define LOADROW(r, m1, m0, p1)                                   \
    {                                                            \
        float2 lo = *(const float2*)&s[(r)][2 * tx];             \
        float2 hi = *(const float2*)&s[(r)][2 * tx + 2];         \
        (m1) = pack2(lo.x, lo.y);                                \
        (p1) = pack2(hi.x, hi.y);                                \
        (m0) = pack2(lo.y, hi.x);                                \
    }

    u64 a0, a1, a2, e0, e1, e2;
    LOADROW(rbase + 0, a0, a1, a2);
    LOADROW(rbase + 1, e0, e1, e2);

#pragma unroll
    for (int lr = 0; lr < ROWS / 2; lr++) {
        u64 c0, c1, c2;
        LOADROW(rbase + lr + 2, c0, c1, c2);

        u64 acc = mul2(a0, w2p[0]);
        acc = fma2(a1, w2p[1], acc);
        acc = fma2(a2, w2p[2], acc);
        acc = fma2(e0, w2p[3], acc);
        acc = fma2(e1, w2p[4], acc);
        acc = fma2(e2, w2p[5], acc);
        acc = fma2(c0, w2p[6], acc);
        acc = fma2(c1, w2p[7], acc);
        acc = fma2(c2, w2p[8], acc);

        stcs64(op + (size_t)lr * Wv, acc);   // streaming: don't evict x from L2

        a0 = e0; a1 = e1; a2 = e2;
        e0 = c0; e1 = c1; e2 = c2;
    }
#undef LOADROW
}

// ---------------------------------------------------------------------------
extern "C" void kernel_launch(void* const* d_in, const int* in_sizes, int n_in,
                              void* d_out, int out_size) {
    const float* x  = (const float*)d_in[0];
    const float* w1 = (const float*)d_in[1];
    const float* b1 = (const float*)d_in[2];
    const float* w2 = (const float*)d_in[3];
    const float* b2 = (const float*)d_in[4];
    float* out = (float*)d_out;

    pool_kernel<<<Bv * Cv, 256>>>(x);
    h_kernel<<<Bv, 128>>>(w1, b1);
    kern_kernel<<<Bv * 36, 128>>>(w2, b2);
    conv_kernel<<<Bv * Cv * (Hv / ROWS), dim3(64, 2)>>>(x, out);
}